// round 2
// baseline (speedup 1.0000x reference)
#include <cuda_runtime.h>
#include <math.h>

// ---------------- problem constants ----------------
#define BATCH 32
#define SEQL  128
#define EMB   768
#define HID   512
#define FH    2048          // 4*HID
#define NPTS  1024
#define PDIM  256
#define NHEAD 4
#define HDIM  128
#define NBLK  5
#define NSEG  4
#define ROWS  (BATCH*SEQL)  // 4096
#define SCALE_ATT 0.08838834764831845f  // 1/sqrt(128)
#define NCTA_L 140          // persistent LSTM grid (28 per block * 5)

// ---------------- scratch (device globals; no allocation allowed) ----------------
__device__ float d_mid  [NBLK * ROWS * HID];
__device__ float d_hmlp [NBLK * ROWS * HID];
__device__ float d_G    [NBLK * ROWS * FH];
__device__ float d_h0seq[NBLK * ROWS * HID];
__device__ float d_h1seq[NBLK * ROWS * HID];
__device__ float d_hst  [2 * NBLK * BATCH * HID];
__device__ float d_bout [NBLK * BATCH * HID];
__device__ float d_kbuf [NSEG * BATCH * NPTS * HID];
__device__ float d_vbuf [NSEG * BATCH * NPTS * HID];
__device__ float d_qbuf [NSEG * BATCH * HID];
__device__ float d_abuf [NSEG * BATCH * HID];
__device__ unsigned int g_barcnt;
__device__ unsigned int g_barphase;

// ---------------- 128x128x8 double-buffered SGEMM ----------------
// C = act(A@W + b1 + b2). A: MxK row-major, W: KxN row-major.
// Requires M%128==0, N%128==0, K%8==0. Batched via blockIdx.z.
__global__ __launch_bounds__(256, 1)
void k_gemm(const float* __restrict__ A, const float* __restrict__ W,
            const float* __restrict__ b1, const float* __restrict__ b2,
            float* __restrict__ C,
            int M, int N, int K,
            long sA, long sW, long sB, long sC, int act)
{
    int z = blockIdx.z;
    A += z * sA; W += z * sW; C += z * sC;
    const float* bias1 = b1 ? b1 + z * sB : nullptr;
    const float* bias2 = b2 ? b2 + z * sB : nullptr;

    __shared__ float As[2][8][128];
    __shared__ float Bs[2][8][128];

    int tid = threadIdx.x;
    int tx = tid & 15, ty = tid >> 4;
    long m0 = (long)blockIdx.y * 128, n0 = (long)blockIdx.x * 128;

    int ar = tid >> 1, ac = (tid & 1) * 4;     // A: 128 rows x 8 cols
    int br = tid >> 5, bc = (tid & 31) * 4;    // B: 8 rows x 128 cols

    const float* Ag = A + (m0 + ar) * K + ac;
    const float* Bg = W + (long)br * N + n0 + bc;

    float4 apre = *(const float4*)Ag;
    float4 bpre = *(const float4*)Bg;
    As[0][ac + 0][ar] = apre.x;
    As[0][ac + 1][ar] = apre.y;
    As[0][ac + 2][ar] = apre.z;
    As[0][ac + 3][ar] = apre.w;
    *(float4*)&Bs[0][br][bc] = bpre;
    __syncthreads();

    float acc[8][8] = {};
    int buf = 0;

    for (int k0 = 8; k0 <= K; k0 += 8) {
        if (k0 < K) {
            apre = *(const float4*)(Ag + k0);
            bpre = *(const float4*)(Bg + (long)k0 * N);
        }
        #pragma unroll
        for (int k = 0; k < 8; k++) {
            float a[8], b[8];
            *(float4*)&a[0] = *(const float4*)&As[buf][k][ty * 4];
            *(float4*)&a[4] = *(const float4*)&As[buf][k][64 + ty * 4];
            *(float4*)&b[0] = *(const float4*)&Bs[buf][k][tx * 4];
            *(float4*)&b[4] = *(const float4*)&Bs[buf][k][64 + tx * 4];
            #pragma unroll
            for (int i = 0; i < 8; i++)
                #pragma unroll
                for (int j = 0; j < 8; j++)
                    acc[i][j] += a[i] * b[j];
        }
        if (k0 < K) {
            buf ^= 1;
            As[buf][ac + 0][ar] = apre.x;
            As[buf][ac + 1][ar] = apre.y;
            As[buf][ac + 2][ar] = apre.z;
            As[buf][ac + 3][ar] = apre.w;
            *(float4*)&Bs[buf][br][bc] = bpre;
            __syncthreads();
        }
    }

    #pragma unroll
    for (int ih = 0; ih < 2; ih++) {
        #pragma unroll
        for (int r = 0; r < 4; r++) {
            long m = m0 + ih * 64 + ty * 4 + r;
            #pragma unroll
            for (int jh = 0; jh < 2; jh++) {
                int n = jh * 64 + tx * 4;
                float v[4];
                #pragma unroll
                for (int j = 0; j < 4; j++) {
                    float x = acc[ih * 4 + r][jh * 4 + j];
                    int nn = n + j;
                    if (bias1) x += bias1[n0 + nn];
                    if (bias2) x += bias2[n0 + nn];
                    if (act == 1) x = (x > 0.f) ? x : 0.01f * x;
                    v[j] = x;
                }
                *(float4*)&C[m * N + n0 + n] = *(float4*)v;
            }
        }
    }
}

// ---------------- grid barrier ----------------
__global__ void k_barinit() { g_barcnt = 0; g_barphase = 0; }

__device__ __forceinline__ void grid_barrier()
{
    __syncthreads();
    if (threadIdx.x == 0) {
        unsigned ph = *(volatile unsigned*)&g_barphase;
        __threadfence();
        unsigned arr = atomicAdd(&g_barcnt, 1u);
        if (arr == (unsigned)NCTA_L - 1) {
            g_barcnt = 0;
            __threadfence();
            *(volatile unsigned*)&g_barphase = ph + 1;
        } else {
            while (*(volatile unsigned*)&g_barphase == ph) __nanosleep(64);
        }
    }
    __syncthreads();
}

// ---------------- persistent LSTM (one layer, 128 steps) ----------------
// CTA owns block i, U hidden units starting at u0 (columns q*512+u0+u, q=0..3).
// h double-buffered in global, c resident in smem, Whh streamed from L2.
template<int U>
__device__ void lstm_body(int i, int u0, const float* __restrict__ Whh,
                          const float* __restrict__ G,
                          float* __restrict__ hseq,
                          float* __restrict__ hb0, float* __restrict__ hb1)
{
    constexpr int C = U / 4;        // cols per thread (tx dim)
    constexpr int COLS = 4 * U;
    __shared__ float Wsh[16][COLS];
    __shared__ float hsh[16][32];
    __shared__ float gsh[32][COLS];
    __shared__ float csh[32][U];

    int tid = threadIdx.x;
    int tx = tid & 15, ty = tid >> 4;   // ty 0..7 -> rows ty*4..ty*4+3

    // zero owned state
    for (int s = tid; s < 32 * U; s += 128) {
        int b = s / U, u = s % U;
        csh[b][u] = 0.f;
        hb0[((long)i * 32 + b) * HID + u0 + u] = 0.f;
    }
    grid_barrier();

    for (int t = 0; t < SEQL; t++) {
        const float* hin = (t & 1) ? hb1 : hb0;
        float* hout      = (t & 1) ? hb0 : hb1;
        const float* hrow = hin + (long)i * 32 * HID;

        float acc[4][C];
        #pragma unroll
        for (int r = 0; r < 4; r++)
            #pragma unroll
            for (int c = 0; c < C; c++) acc[r][c] = 0.f;

        for (int k0 = 0; k0 < HID; k0 += 16) {
            // stream W tile: 16 x COLS
            for (int f = tid; f < 16 * U; f += 128) {
                int k = f / U, rest = f % U;
                int q = rest / C, j = rest % C;
                float4 w = *(const float4*)(Whh + (long)(k0 + k) * FH + q * HID + u0 + j * 4);
                *(float4*)&Wsh[k][q * U + j * 4] = w;
            }
            // h tile: 16 x 32 (transposed into smem)
            {
                int b = tid >> 2, kk = (tid & 3) * 4;
                float4 hv4 = *(const float4*)(hrow + (long)b * HID + k0 + kk);
                hsh[kk + 0][b] = hv4.x; hsh[kk + 1][b] = hv4.y;
                hsh[kk + 2][b] = hv4.z; hsh[kk + 3][b] = hv4.w;
            }
            __syncthreads();
            #pragma unroll
            for (int k = 0; k < 16; k++) {
                float hv[4];
                *(float4*)hv = *(const float4*)&hsh[k][ty * 4];
                float wv[C];
                #pragma unroll
                for (int c = 0; c < C; c++) wv[c] = Wsh[k][tx * C + c];
                #pragma unroll
                for (int r = 0; r < 4; r++)
                    #pragma unroll
                    for (int c = 0; c < C; c++)
                        acc[r][c] += hv[r] * wv[c];
            }
            __syncthreads();
        }

        // add precomputed input projection, stage for gate exchange
        #pragma unroll
        for (int r = 0; r < 4; r++) {
            int b = ty * 4 + r;
            #pragma unroll
            for (int c = 0; c < C; c++) {
                int lc = tx * C + c;
                int q = lc / U, u = lc % U;
                float g = G[(((long)i * 32 + b) * SEQL + t) * FH + q * HID + u0 + u];
                gsh[b][lc] = acc[r][c] + g;
            }
        }
        __syncthreads();

        // gates (units owned locally: i/f/g/o all in this CTA)
        for (int s = tid; s < 32 * U; s += 128) {
            int b = s / U, u = s % U;
            float ip = gsh[b][u];
            float fp = gsh[b][U + u];
            float gp = gsh[b][2 * U + u];
            float op = gsh[b][3 * U + u];
            float cold = csh[b][u];
            float ig = 1.f / (1.f + __expf(-ip));
            float fg = 1.f / (1.f + __expf(-fp));
            float og = 1.f / (1.f + __expf(-op));
            float cn = fg * cold + ig * tanhf(gp);
            float hn = og * tanhf(cn);
            csh[b][u] = cn;
            hout[((long)i * 32 + b) * HID + u0 + u] = hn;
            hseq[(((long)i * 32 + b) * SEQL + t) * HID + u0 + u] = hn;
        }
        grid_barrier();
    }
}

__global__ __launch_bounds__(128, 1)
void k_lstm(const float* __restrict__ lstm_Whh, int layer,
            const float* __restrict__ G, float* __restrict__ hseq,
            float* __restrict__ hb)
{
    int cid = blockIdx.x;
    int i = cid / 28, loc = cid % 28;    // 16 CTAs of 20 units + 12 of 16 units = 512
    const float* Whh = lstm_Whh + ((long)i * 2 + layer) * HID * FH;
    float* hb0 = hb;
    float* hb1 = hb + (long)NBLK * BATCH * HID;
    if (loc < 16) lstm_body<20>(i, loc * 20, Whh, G, hseq, hb0, hb1);
    else          lstm_body<16>(i, 320 + (loc - 16) * 16, Whh, G, hseq, hb0, hb1);
}

// ---------------- gather last timestep + linear ----------------
__global__ void k_blkout(const float* __restrict__ h1seq, const int* __restrict__ text_length,
                         const float* __restrict__ linW, const float* __restrict__ linb,
                         float* __restrict__ bout)
{
    int i = blockIdx.x, b = blockIdx.y, tid = threadIdx.x;
    int len = text_length[b * NBLK + i];
    const float* last = h1seq + (((long)i * BATCH + b) * SEQL + (len - 1)) * HID;
    __shared__ float lsh[HID];
    lsh[tid] = last[tid];
    lsh[tid + 256] = last[tid + 256];
    __syncthreads();
    const float* W = linW + (long)i * HID * HID;
    for (int n = tid; n < HID; n += 256) {
        float s = linb[i * HID + n];
        #pragma unroll 4
        for (int k = 0; k < HID; k++) s += lsh[k] * W[(long)k * HID + n];
        bout[((long)i * BATCH + b) * HID + n] = s;
    }
}

// ---------------- q projection ----------------
__global__ void k_qproj(const float* __restrict__ bout, const float* __restrict__ Wq,
                        const float* __restrict__ bq, float* __restrict__ q)
{
    int s = blockIdx.x, b = blockIdx.y, tid = threadIdx.x;
    __shared__ float z[HID];
    const float* zin = bout + (((long)(s + 1) * BATCH) + b) * HID;
    z[tid] = zin[tid];
    z[tid + 256] = zin[tid + 256];
    __syncthreads();
    const float* W = Wq + (long)s * HID * HID;
    for (int n = tid; n < HID; n += 256) {
        float acc = bq[s * HID + n];
        #pragma unroll 4
        for (int k = 0; k < HID; k++) acc += z[k] * W[(long)k * HID + n];
        q[((long)s * BATCH + b) * HID + n] = acc;
    }
}

// ---------------- masked attention per (head, batch, seg) ----------------
__global__ void k_attn(const float* __restrict__ q, const float* __restrict__ kbuf,
                       const float* __restrict__ vbuf, const int* __restrict__ pmask,
                       float* __restrict__ aout)
{
    int h = blockIdx.x, b = blockIdx.y, s = blockIdx.z;
    int tid = threadIdx.x;
    __shared__ float qsh[HDIM];
    __shared__ float sc[NPTS];
    __shared__ float red[256];

    long rowbase = ((long)s * BATCH + b) * NPTS;
    const float* qrow = q + ((long)s * BATCH + b) * HID + h * HDIM;
    if (tid < HDIM) qsh[tid] = qrow[tid];
    __syncthreads();

    float lmax = -1e30f;
    for (int n = tid; n < NPTS; n += 256) {
        const float* kr = kbuf + (rowbase + n) * HID + h * HDIM;
        float d = 0.f;
        #pragma unroll
        for (int c = 0; c < HDIM; c += 4) {
            float4 k4 = *(const float4*)(kr + c);
            float4 q4 = *(const float4*)(qsh + c);
            d += k4.x * q4.x + k4.y * q4.y + k4.z * q4.z + k4.w * q4.w;
        }
        float v = (pmask[b * NPTS + n] == s + 1) ? d * SCALE_ATT : -1e9f;
        sc[n] = v;
        lmax = fmaxf(lmax, v);
    }
    red[tid] = lmax; __syncthreads();
    for (int off = 128; off > 0; off >>= 1) {
        if (tid < off) red[tid] = fmaxf(red[tid], red[tid + off]);
        __syncthreads();
    }
    float mx = red[0];
    __syncthreads();

    float lsum = 0.f;
    for (int n = tid; n < NPTS; n += 256) {
        float e = expf(sc[n] - mx);
        sc[n] = e;
        lsum += e;
    }
    red[tid] = lsum; __syncthreads();
    for (int off = 128; off > 0; off >>= 1) {
        if (tid < off) red[tid] += red[tid + off];
        __syncthreads();
    }
    float inv = 1.f / red[0];
    __syncthreads();

    int d = tid & 127, half = tid >> 7;
    const float* vb = vbuf + rowbase * HID + h * HDIM + d;
    float acc = 0.f;
    int nbeg = half * 512;
    #pragma unroll 4
    for (int n = nbeg; n < nbeg + 512; n++) acc += sc[n] * vb[(long)n * HID];
    red[tid] = acc; __syncthreads();
    if (tid < HDIM)
        aout[((long)s * BATCH + b) * HID + h * HDIM + tid] = (red[tid] + red[tid + 128]) * inv;
}

// ---------------- seg output ----------------
__global__ void k_segfinal(const float* __restrict__ abuf, const float* __restrict__ Wo,
                           const float* __restrict__ bo, const float* __restrict__ bout,
                           const int* __restrict__ pmask, float* __restrict__ out)
{
    int s = blockIdx.x, b = blockIdx.y, tid = threadIdx.x;
    __shared__ float ash[HID];
    __shared__ int anyf;
    if (tid == 0) anyf = 0;
    __syncthreads();
    int loc = 0;
    for (int n = tid; n < NPTS; n += 256)
        if (pmask[b * NPTS + n] == s + 1) loc = 1;
    if (loc) anyf = 1;
    const float* ar = abuf + ((long)s * BATCH + b) * HID;
    ash[tid] = ar[tid];
    ash[tid + 256] = ar[tid + 256];
    __syncthreads();
    const float* W = Wo + (long)s * HID * HID;
    int has = anyf;
    for (int n = tid; n < HID; n += 256) {
        float v = 0.f;
        if (has) {
            v = bo[s * HID + n];
            #pragma unroll 4
            for (int k = 0; k < HID; k++) v += ash[k] * W[(long)k * HID + n];
        }
        out[(long)(1 + s) * (BATCH * HID) + b * HID + n] =
            bout[(((long)(s + 1) * BATCH) + b) * HID + n] + v;
    }
}

// ---------------- classifier + output copies ----------------
__global__ void k_cls(const float* __restrict__ bout,
                      const float* __restrict__ W1, const float* __restrict__ b1,
                      const float* __restrict__ W2, const float* __restrict__ b2,
                      const float* __restrict__ W3, const float* __restrict__ b3,
                      float* __restrict__ out)
{
    int b = blockIdx.x, tid = threadIdx.x;  // 128 threads
    __shared__ float tg[HID];
    __shared__ float h1[128];
    __shared__ float h2[16];
    for (int k = tid; k < HID; k += 128) tg[k] = bout[(long)b * HID + k];
    __syncthreads();
    for (int k = tid; k < HID; k += 128) {
        out[(long)b * HID + k] = tg[k];
        out[5L * BATCH * HID + BATCH * 3 + (long)b * HID + k] = tg[k];
    }
    float s1 = b1[tid];
    #pragma unroll 4
    for (int k = 0; k < HID; k++) s1 += tg[k] * W1[k * 128 + tid];
    h1[tid] = fmaxf(s1, 0.f);
    __syncthreads();
    if (tid < 16) {
        float s2 = b2[tid];
        #pragma unroll
        for (int k = 0; k < 128; k++) s2 += h1[k] * W2[k * 16 + tid];
        h2[tid] = fmaxf(s2, 0.f);
    }
    __syncthreads();
    if (tid < 3) {
        float s3 = b3[tid];
        #pragma unroll
        for (int k = 0; k < 16; k++) s3 += h2[k] * W3[k * 3 + tid];
        out[5L * BATCH * HID + b * 3 + tid] = s3;
    }
}

// ---------------- launch ----------------
extern "C" void kernel_launch(void* const* d_in, const int* in_sizes, int n_in,
                              void* d_out, int out_size)
{
    (void)in_sizes; (void)n_in; (void)out_size;
    const float* tfeat[5];
    for (int i = 0; i < 5; i++) tfeat[i] = (const float*)d_in[i];
    const int*   text_length = (const int*)d_in[5];
    const float* radar       = (const float*)d_in[6];
    const int*   pmask       = (const int*)d_in[7];
    const float* blk_W1  = (const float*)d_in[8];
    const float* blk_b1  = (const float*)d_in[9];
    const float* blk_W2  = (const float*)d_in[10];
    const float* blk_b2  = (const float*)d_in[11];
    const float* lstm_Wih = (const float*)d_in[12];
    const float* lstm_Whh = (const float*)d_in[13];
    const float* lstm_bih = (const float*)d_in[14];
    const float* lstm_bhh = (const float*)d_in[15];
    const float* blk_lin_W = (const float*)d_in[16];
    const float* blk_lin_b = (const float*)d_in[17];
    const float* att_Wq = (const float*)d_in[18];
    const float* att_bq = (const float*)d_in[19];
    const float* att_Wk = (const float*)d_in[20];
    const float* att_bk = (const float*)d_in[21];
    const float* att_Wv = (const float*)d_in[22];
    const float* att_bv = (const float*)d_in[23];
    const float* att_Wo = (const float*)d_in[24];
    const float* att_bo = (const float*)d_in[25];
    const float* cls_W1 = (const float*)d_in[26];
    const float* cls_b1 = (const float*)d_in[27];
    const float* cls_W2 = (const float*)d_in[28];
    const float* cls_b2 = (const float*)d_in[29];
    const float* cls_W3 = (const float*)d_in[30];
    const float* cls_b3 = (const float*)d_in[31];
    float* out = (float*)d_out;

    float *g_mid, *g_h, *g_G, *g_h0, *g_h1, *g_hs, *g_bo, *g_k, *g_v, *g_q, *g_a;
    cudaGetSymbolAddress((void**)&g_mid, d_mid);
    cudaGetSymbolAddress((void**)&g_h,   d_hmlp);
    cudaGetSymbolAddress((void**)&g_G,   d_G);
    cudaGetSymbolAddress((void**)&g_h0,  d_h0seq);
    cudaGetSymbolAddress((void**)&g_h1,  d_h1seq);
    cudaGetSymbolAddress((void**)&g_hs,  d_hst);
    cudaGetSymbolAddress((void**)&g_bo,  d_bout);
    cudaGetSymbolAddress((void**)&g_k,   d_kbuf);
    cudaGetSymbolAddress((void**)&g_v,   d_vbuf);
    cudaGetSymbolAddress((void**)&g_q,   d_qbuf);
    cudaGetSymbolAddress((void**)&g_a,   d_abuf);

    const long HSZ = (long)ROWS * HID;
    const long GSZ = (long)ROWS * FH;

    // 1) pre-MLP: leaky_relu(x@W1+b1) then @W2+b2
    for (int i = 0; i < 5; i++)
        k_gemm<<<dim3(4, 32, 1), 256>>>(tfeat[i], blk_W1 + (long)i * EMB * HID,
                                        blk_b1 + i * HID, nullptr,
                                        g_mid + (long)i * HSZ,
                                        ROWS, HID, EMB, 0, 0, 0, 0, 1);
    k_gemm<<<dim3(4, 32, 5), 256>>>(g_mid, blk_W2, blk_b2, nullptr, g_h,
                                    ROWS, HID, HID, HSZ, (long)HID * HID, HID, HSZ, 0);

    // 2) layer-0 input projections, then persistent LSTM layer 0
    k_gemm<<<dim3(16, 32, 5), 256>>>(g_h, lstm_Wih, lstm_bih, lstm_bhh, g_G,
                                     ROWS, FH, HID, HSZ, (long)2 * HID * FH, (long)2 * FH, GSZ, 0);
    k_barinit<<<1, 1>>>();
    k_lstm<<<NCTA_L, 128>>>(lstm_Whh, 0, g_G, g_h0, g_hs);

    // 3) layer-1 input projections, then persistent LSTM layer 1
    k_gemm<<<dim3(16, 32, 5), 256>>>(g_h0, lstm_Wih + (long)HID * FH,
                                     lstm_bih + FH, lstm_bhh + FH, g_G,
                                     ROWS, FH, HID, HSZ, (long)2 * HID * FH, (long)2 * FH, GSZ, 0);
    k_barinit<<<1, 1>>>();
    k_lstm<<<NCTA_L, 128>>>(lstm_Whh, 1, g_G, g_h1, g_hs);

    // 4) gather last + linear
    k_blkout<<<dim3(5, 32), 256>>>(g_h1, text_length, blk_lin_W, blk_lin_b, g_bo);

    // 5) K/V projections (A shared across segs: strideA = 0)
    k_gemm<<<dim3(4, 256, 4), 256>>>(radar, att_Wk, att_bk, nullptr, g_k,
                                     BATCH * NPTS, HID, PDIM, 0, (long)PDIM * HID, HID,
                                     (long)BATCH * NPTS * HID, 0);
    k_gemm<<<dim3(4, 256, 4), 256>>>(radar, att_Wv, att_bv, nullptr, g_v,
                                     BATCH * NPTS, HID, PDIM, 0, (long)PDIM * HID, HID,
                                     (long)BATCH * NPTS * HID, 0);

    // 6) q projection, attention, seg output
    k_qproj<<<dim3(4, 32), 256>>>(g_bo, att_Wq, att_bq, g_q);
    k_attn<<<dim3(NHEAD, BATCH, NSEG), 256>>>(g_q, g_k, g_v, pmask, g_a);
    k_segfinal<<<dim3(4, 32), 256>>>(g_a, att_Wo, att_bo, g_bo, pmask, out);

    // 7) classifier + copies of text_general / cls_feat
    k_cls<<<32, 128>>>(g_bo, cls_W1, cls_b1, cls_W2, cls_b2, cls_W3, cls_b3, out);
}